// round 1
// baseline (speedup 1.0000x reference)
#include <cuda_runtime.h>
#include <cuda_bf16.h>
#include <math.h>

// Problem constants (fixed by the reference)
#define INF   64
#define HID   128
#define LAT   32
#define HARM  8
#define NLAY  3
#define NG    64
#define NMAX  50000
#define EMAX  1600000

// ---------------- device scratch (no allocations allowed) ----------------
__device__ float g_bufA[NMAX * HID];
__device__ float g_bufB[NMAX * HID];
__device__ float g_dinv[NMAX];
__device__ int   g_deg[NMAX];
__device__ float g_wt_embed[INF * HARM * 2 * HID];          // [K=1024][128]
__device__ float g_wt_mp[NLAY][HID * HARM * 2 * HID];       // [K=2048][128] each
__device__ float g_wt_read[HID * HARM * 2 * LAT];           // [K=2048][32]
__device__ float g_pool[NG * HID];
__device__ float g_cnt[NG];
__device__ float g_y[NG * HID];

// ---------------- weight transpose: W[2,OUT,INF,H] -> Wt[(i*H+h)*2+s][OUT] ----
__global__ void transpose_w(const float* __restrict__ W, float* __restrict__ Wt,
                            int OUT, int IN_F) {
    int idx = blockIdx.x * blockDim.x + threadIdx.x;
    int total = 2 * OUT * IN_F * HARM;
    if (idx >= total) return;
    int o = idx % OUT;
    int k = idx / OUT;
    int s = k & 1;
    int h = (k >> 1) & (HARM - 1);
    int i = k >> 4;               // k / (2*H)
    Wt[idx] = W[(((size_t)s * OUT + o) * IN_F + i) * HARM + h];
}

// ---------------- degree / dinv ----------------
__global__ void deg_kernel(const int* __restrict__ ei, int* __restrict__ deg, int E) {
    int e = blockIdx.x * blockDim.x + threadIdx.x;
    if (e < E) atomicAdd(&deg[ei[E + e]], 1);
}
__global__ void dinv_kernel(const int* __restrict__ deg, float* __restrict__ dinv, int n) {
    int i = blockIdx.x * blockDim.x + threadIdx.x;
    if (i < n) dinv[i] = rsqrtf((float)(deg[i] + 1));  // +1 = self loop
}

// ---------------- fused KAN GEMM: Y[N,128] = Phi(X) @ Wt ----------------
// Phi(X)[m, i*16 + 2h+s] = (s==0 ? cos : sin)((h+1) * X[m,i])
template <int KF>
__launch_bounds__(256, 2)
__global__ void kan_gemm(const float* __restrict__ X, const float* __restrict__ Wt,
                         float* __restrict__ Y, int n) {
    __shared__ float sh_phi[16][HID];
    __shared__ float sh_w[16][HID];

    const int tid = threadIdx.x;
    const int bm  = blockIdx.x * 128;
    const int tx  = tid & 15;    // output col group
    const int ty  = tid >> 4;    // node row group

    float acc[8][8];
#pragma unroll
    for (int r = 0; r < 8; r++)
#pragma unroll
        for (int c = 0; c < 8; c++) acc[r][c] = 0.f;

    for (int i = 0; i < KF; i++) {
        if (tid < 128) {
            // produce Phi tile for feature i (one node per thread)
            int m = bm + tid;
            float x = (m < n) ? X[(size_t)m * KF + i] : 0.f;
            float s1, c1;
            sincosf(x, &s1, &c1);
            float cp = 1.f, sp = 0.f, cc = c1, sc = s1;
#pragma unroll
            for (int h = 0; h < HARM; h++) {
                sh_phi[2 * h][tid]     = cc;
                sh_phi[2 * h + 1][tid] = sc;
                float cn = 2.f * c1 * cc - cp;
                float sn = 2.f * c1 * sc - sp;
                cp = cc; sp = sc; cc = cn; sc = sn;
            }
        } else {
            // stage W tile [16][128] (coalesced float4)
            int t = tid - 128;
            const float4* src = (const float4*)(Wt + (size_t)i * 16 * HID);
            float4* dst = (float4*)(&sh_w[0][0]);
#pragma unroll
            for (int j = 0; j < 4; j++) dst[t + j * 128] = src[t + j * 128];
        }
        __syncthreads();

#pragma unroll
        for (int kk = 0; kk < 16; kk++) {
            float4 a0 = *(const float4*)(&sh_phi[kk][ty * 8]);
            float4 a1 = *(const float4*)(&sh_phi[kk][ty * 8 + 4]);
            float4 b0 = *(const float4*)(&sh_w[kk][tx * 8]);
            float4 b1 = *(const float4*)(&sh_w[kk][tx * 8 + 4]);
            float a[8] = {a0.x, a0.y, a0.z, a0.w, a1.x, a1.y, a1.z, a1.w};
            float b[8] = {b0.x, b0.y, b0.z, b0.w, b1.x, b1.y, b1.z, b1.w};
#pragma unroll
            for (int r = 0; r < 8; r++)
#pragma unroll
                for (int c = 0; c < 8; c++)
                    acc[r][c] = fmaf(a[r], b[c], acc[r][c]);
        }
        __syncthreads();
    }

    // write out
#pragma unroll
    for (int r = 0; r < 8; r++) {
        int m = bm + ty * 8 + r;
        if (m < n) {
            float4 v0 = make_float4(acc[r][0], acc[r][1], acc[r][2], acc[r][3]);
            float4 v1 = make_float4(acc[r][4], acc[r][5], acc[r][6], acc[r][7]);
            float4* out = (float4*)(Y + (size_t)m * HID + tx * 8);
            out[0] = v0;
            out[1] = v1;
        }
    }
}

// ---------------- scatter: dst[col] += dinv[row]*dinv[col] * src[row] ------
__global__ void scatter_kernel(const float* __restrict__ src, float* __restrict__ dst,
                               const int* __restrict__ ei, const float* __restrict__ dinv,
                               int E, int Etot) {
    int gw   = (blockIdx.x * blockDim.x + threadIdx.x) >> 5;
    int lane = threadIdx.x & 31;
    if (gw >= Etot) return;
    int r, c;
    if (gw < E) { r = ei[gw]; c = ei[E + gw]; }
    else        { r = c = gw - E; }                      // self loop
    float nrm = dinv[r] * dinv[c];
    float4 v = ((const float4*)(src + (size_t)r * HID))[lane];
    float* d = dst + (size_t)c * HID + lane * 4;
    atomicAdd(d + 0, nrm * v.x);
    atomicAdd(d + 1, nrm * v.y);
    atomicAdd(d + 2, nrm * v.z);
    atomicAdd(d + 3, nrm * v.w);
}

// ---------------- mean pool (batch is sorted -> run-length flush) ----------
__global__ void pool_kernel(const float* __restrict__ h, const int* __restrict__ batch,
                            float* __restrict__ pool, float* __restrict__ cnt, int n) {
    int c  = threadIdx.x;         // 0..127
    int n0 = blockIdx.x * 256;
    if (n0 >= n) return;
    int nend = min(n0 + 256, n);
    float acc = 0.f;
    int cur = batch[n0];
    int runStart = n0;
    for (int m = n0; m < nend; m++) {
        int b = batch[m];
        if (b != cur) {
            atomicAdd(&pool[cur * HID + c], acc);
            if (c == 0) atomicAdd(&cnt[cur], (float)(m - runStart));
            acc = 0.f; cur = b; runStart = m;
        }
        acc += h[(size_t)m * HID + c];
    }
    atomicAdd(&pool[cur * HID + c], acc);
    if (c == 0) atomicAdd(&cnt[cur], (float)(nend - runStart));
}

__global__ void mean_kernel(const float* __restrict__ pool, const float* __restrict__ cnt,
                            float* __restrict__ y) {
    int idx = blockIdx.x * blockDim.x + threadIdx.x;
    if (idx >= NG * HID) return;
    int g = idx >> 7;
    y[idx] = pool[idx] / fmaxf(cnt[g], 1.0f);
}

// ---------------- readout KAN: [64,128] -> [64,32] -------------------------
__global__ void kan_read_kernel(const float* __restrict__ Y, const float* __restrict__ Wt,
                                float* __restrict__ out) {
    int idx = blockIdx.x * blockDim.x + threadIdx.x;
    if (idx >= NG * LAT) return;
    int g = idx >> 5;
    int o = idx & 31;
    float acc = 0.f;
    for (int i = 0; i < HID; i++) {
        float x = Y[g * HID + i];
        float s1, c1;
        sincosf(x, &s1, &c1);
        float cp = 1.f, sp = 0.f, cc = c1, sc = s1;
#pragma unroll
        for (int h = 0; h < HARM; h++) {
            const float* w = Wt + ((size_t)(i * HARM + h) * 2) * LAT;
            acc = fmaf(cc, w[o], acc);
            acc = fmaf(sc, w[LAT + o], acc);
            float cn = 2.f * c1 * cc - cp;
            float sn = 2.f * c1 * sc - sp;
            cp = cc; sp = sc; cc = cn; sc = sn;
        }
    }
    out[idx] = acc;
}

// ---------------- launch ----------------------------------------------------
extern "C" void kernel_launch(void* const* d_in, const int* in_sizes, int n_in,
                              void* d_out, int out_size) {
    const float* features = (const float*)d_in[0];
    const int*   ei       = (const int*)d_in[1];
    const int*   batch    = (const int*)d_in[2];
    const float* W_embed  = (const float*)d_in[3];
    const float* W_mp     = (const float*)d_in[4];
    const float* W_read   = (const float*)d_in[5];
    float*       out      = (float*)d_out;

    const int n = in_sizes[0] / INF;
    const int E = in_sizes[1] / 2;
    const int Etot = E + n;

    float *p_bufA, *p_bufB, *p_dinv, *p_pool, *p_cnt, *p_y;
    float *p_wte, *p_wtm, *p_wtr;
    int   *p_deg;
    cudaGetSymbolAddress((void**)&p_bufA, g_bufA);
    cudaGetSymbolAddress((void**)&p_bufB, g_bufB);
    cudaGetSymbolAddress((void**)&p_dinv, g_dinv);
    cudaGetSymbolAddress((void**)&p_deg,  g_deg);
    cudaGetSymbolAddress((void**)&p_wte,  g_wt_embed);
    cudaGetSymbolAddress((void**)&p_wtm,  g_wt_mp);
    cudaGetSymbolAddress((void**)&p_wtr,  g_wt_read);
    cudaGetSymbolAddress((void**)&p_pool, g_pool);
    cudaGetSymbolAddress((void**)&p_cnt,  g_cnt);
    cudaGetSymbolAddress((void**)&p_y,    g_y);

    // 1) transpose weights to [K, out] (coalesced B for the GEMMs)
    {
        int tot = 2 * HID * INF * HARM;
        transpose_w<<<(tot + 255) / 256, 256>>>(W_embed, p_wte, HID, INF);
    }
    for (int l = 0; l < NLAY; l++) {
        int tot = 2 * HID * HID * HARM;
        transpose_w<<<(tot + 255) / 256, 256>>>(W_mp + (size_t)l * tot, p_wtm + (size_t)l * tot, HID, HID);
    }
    {
        int tot = 2 * LAT * HID * HARM;
        transpose_w<<<(tot + 255) / 256, 256>>>(W_read, p_wtr, LAT, HID);
    }

    // 2) degrees -> dinv
    cudaMemsetAsync(p_deg, 0, (size_t)n * sizeof(int));
    deg_kernel<<<(E + 255) / 256, 256>>>(ei, p_deg, E);
    dinv_kernel<<<(n + 255) / 256, 256>>>(p_deg, p_dinv, n);

    // 3) embedding KAN
    int gblocks = (n + 127) / 128;
    kan_gemm<INF><<<gblocks, 256>>>(features, p_wte, p_bufA, n);

    // 4) message-passing layers
    for (int l = 0; l < NLAY; l++) {
        kan_gemm<HID><<<gblocks, 256>>>(p_bufA, p_wtm + (size_t)l * 2 * HID * HID * HARM, p_bufB, n);
        cudaMemsetAsync(p_bufA, 0, (size_t)n * HID * sizeof(float));
        scatter_kernel<<<(Etot + 7) / 8, 256>>>(p_bufB, p_bufA, ei, p_dinv, E, Etot);
    }

    // 5) mean pool + readout
    cudaMemsetAsync(p_pool, 0, NG * HID * sizeof(float));
    cudaMemsetAsync(p_cnt,  0, NG * sizeof(float));
    pool_kernel<<<(n + 255) / 256, 128>>>(p_bufA, batch, p_pool, p_cnt, n);
    mean_kernel<<<(NG * HID + 255) / 256, 256>>>(p_pool, p_cnt, p_y);
    kan_read_kernel<<<(NG * LAT + 255) / 256, 256>>>(p_y, p_wtr, out);
}